// round 11
// baseline (speedup 1.0000x reference)
#include <cuda_runtime.h>
#include <cuda_bf16.h>
#include <cuda_fp16.h>
#include <math.h>
#include <stdint.h>

// ---------------- problem constants ----------------
#define Bc   2
#define Sc   13294
#define Dc   256
#define Hc   8
#define LVLc 4
#define DFFc 1024
#define NLc  6
#define DHc  32
#define Mc   (Bc*Sc)          // 26588 token rows

// weight elems per layer and per-weight offsets (transposed [N,K] bf16 hi/lo)
#define WPL    753664
#define OFF_VP 0
#define OFF_SO 65536
#define OFF_AW 131072
#define OFF_OP 163840
#define OFF_F1 229376
#define OFF_F2 491520

// ---------------- device scratch (no allocation allowed) ----------------
__device__ float g_src [Mc*Dc];
__device__ __half g_valh[Mc*Dc];          // value fp16 [B,H,S,DH]
__device__ float g_oa  [Mc*384];          // fused: [0,256)=offsets, [256,384)=attn
__device__ float g_tmp [Mc*Dc];
__device__ float g_src2[Mc*Dc];
__device__ __nv_bfloat16 g_srch[Mc*Dc], g_srcl[Mc*Dc];
__device__ __nv_bfloat16 g_qh [Mc*Dc],  g_ql [Mc*Dc];
__device__ __nv_bfloat16 g_s2h[Mc*Dc],  g_s2l[Mc*Dc];
__device__ __nv_bfloat16 g_defh[Mc*Dc], g_defl[Mc*Dc];
__device__ __nv_bfloat16 g_ffnh[Mc*DFFc], g_ffnl[Mc*DFFc];
__device__ __nv_bfloat16 g_wh[NLc*WPL], g_wl[NLc*WPL];

// ---------------- helpers ----------------
__device__ __forceinline__ uint32_t smem_u32(const void* p) {
    uint32_t a;
    asm("{ .reg .u64 t; cvta.to.shared.u64 t, %1; cvt.u32.u64 %0, t; }" : "=r"(a) : "l"(p));
    return a;
}
__device__ __forceinline__ void cp16(uint32_t d, const void* s, int pbytes) {
    asm volatile("cp.async.cg.shared.global [%0], [%1], 16, %2;\n"
        :: "r"(d), "l"(s), "r"(pbytes) : "memory");
}
#define LDM_X4(r0,r1,r2,r3,addr) \
    asm volatile("ldmatrix.sync.aligned.m8n8.x4.shared.b16 {%0,%1,%2,%3}, [%4];" \
        : "=r"(r0),"=r"(r1),"=r"(r2),"=r"(r3) : "r"(addr))
#define LDM_X2(r0,r1,addr) \
    asm volatile("ldmatrix.sync.aligned.m8n8.x2.shared.b16 {%0,%1}, [%2];" \
        : "=r"(r0),"=r"(r1) : "r"(addr))
#define MMA_BF16(c, a, b) \
    asm volatile("mma.sync.aligned.m16n8k16.row.col.f32.bf16.bf16.f32 " \
        "{%0,%1,%2,%3}, {%4,%5,%6,%7}, {%8,%9}, {%0,%1,%2,%3};" \
        : "+f"((c)[0]),"+f"((c)[1]),"+f"((c)[2]),"+f"((c)[3]) \
        : "r"((a)[0]),"r"((a)[1]),"r"((a)[2]),"r"((a)[3]), "r"((b)[0]),"r"((b)[1]))

// ---------------- fused weight prep: all layers, all weights, one launch ----------------
__global__ void wprep_all(const float* __restrict__ vp, const float* __restrict__ so,
                          const float* __restrict__ aw, const float* __restrict__ op,
                          const float* __restrict__ f1, const float* __restrict__ f2,
                          __nv_bfloat16* __restrict__ wh, __nv_bfloat16* __restrict__ wl)
{
    int idx = blockIdx.x * blockDim.x + threadIdx.x;
    if (idx >= NLc * WPL) return;
    int l = idx / WPL, r = idx - l * WPL;
    const float* W; int K, N, off;
    if (r < OFF_SO)      { W = vp + (size_t)l * 65536;  off = OFF_VP; K = 256;  N = 256; }
    else if (r < OFF_AW) { W = so + (size_t)l * 65536;  off = OFF_SO; K = 256;  N = 256; }
    else if (r < OFF_OP) { W = aw + (size_t)l * 32768;  off = OFF_AW; K = 256;  N = 128; }
    else if (r < OFF_F1) { W = op + (size_t)l * 65536;  off = OFF_OP; K = 256;  N = 256; }
    else if (r < OFF_F2) { W = f1 + (size_t)l * 262144; off = OFF_F1; K = 256;  N = 1024; }
    else                 { W = f2 + (size_t)l * 262144; off = OFF_F2; K = 1024; N = 256; }
    int ri = r - off;
    int k = ri / N, n = ri - k * N;
    float v = W[(size_t)k * N + n];
    __nv_bfloat16 h = __float2bfloat16(v);
    size_t dst = (size_t)l * WPL + off + (size_t)n * K + k;
    wh[dst] = h;
    wl[dst] = __float2bfloat16(v - __bfloat162float(h));
}

// ---------------- streaming fp32 -> bf16 hi/lo split (optionally a+b) ----------------
__global__ void split_k(const float4* __restrict__ a, const float4* __restrict__ b,
                        uint2* __restrict__ hi, uint2* __restrict__ lo, int n4)
{
    int i = blockIdx.x * blockDim.x + threadIdx.x;
    if (i >= n4) return;
    float4 v = a[i];
    if (b) { float4 p = b[i]; v.x += p.x; v.y += p.y; v.z += p.z; v.w += p.w; }
    __nv_bfloat162 h01 = __floats2bfloat162_rn(v.x, v.y);
    __nv_bfloat162 h23 = __floats2bfloat162_rn(v.z, v.w);
    __nv_bfloat162 l01 = __floats2bfloat162_rn(v.x - __bfloat162float(h01.x),
                                               v.y - __bfloat162float(h01.y));
    __nv_bfloat162 l23 = __floats2bfloat162_rn(v.z - __bfloat162float(h23.x),
                                               v.w - __bfloat162float(h23.y));
    hi[i] = make_uint2(*(uint32_t*)&h01, *(uint32_t*)&h23);
    lo[i] = make_uint2(*(uint32_t*)&l01, *(uint32_t*)&l23);
}

// ---------------- pipelined tensor GEMM (bf16 split x3, fp32 accum) ----------------
// C = A @ W + bias.  A pre-split (Ah/Al bf16 [M,K]), W as Bh/Bl [N,K].
// CTA tile 128x64, 8 warps (4x2), warp tile 32x32, BK=32, THREE-stage cp.async pipeline.
// EPI: 0=bias fp32; 1=bias+relu -> bf16 hi/lo (Cv,Cv2), N=1024;
//      2=bias -> fp16 transposed [B,H,S,DH]; 3=dual bias fp32, row stride 384.
// smem stage: Ah 10240 | Al 10240 | Bh 5120 | Bl 5120 = 30720 B (row stride 80 B)
#define STG_BYTES 30720
#define NSTAGE    3
#define SMEM_TOT  (NSTAGE*STG_BYTES)

template<int EPI>
__global__ void __launch_bounds__(256, 2)
mgemm_k(const __nv_bfloat16* __restrict__ Ah, const __nv_bfloat16* __restrict__ Al,
        const __nv_bfloat16* __restrict__ Bh, const __nv_bfloat16* __restrict__ Bl,
        const float* __restrict__ bias, const float* __restrict__ bias2,
        void* __restrict__ Cv, void* __restrict__ Cv2,
        int M, int N, int K)
{
    extern __shared__ char sm[];
    const int tid = threadIdx.x, warp = tid >> 5, lane = tid & 31;
    const int m0 = blockIdx.y * 128, n0 = blockIdx.x * 64;
    const int wm = warp >> 1, wn = warp & 1;

    float acc[2][4][4] = {};
    const int nch = K >> 5;

    auto load_stage = [&](int st, int kt) {
        char* base = sm + st * STG_BYTES;
        #pragma unroll
        for (int j = 0; j < 2; ++j) {
            int ci = j * 256 + tid, row = ci >> 2, c = ci & 3;
            int gm = m0 + row;
            int pb = (gm < M) ? 16 : 0;
            int gmc = (gm < M) ? gm : (M - 1);
            const char* sa = (const char*)(Ah + (size_t)gmc * K + kt) + c * 16;
            const char* sl = (const char*)(Al + (size_t)gmc * K + kt) + c * 16;
            cp16(smem_u32(base + row * 80 + c * 16), sa, pb);
            cp16(smem_u32(base + 10240 + row * 80 + c * 16), sl, pb);
        }
        {
            int row = tid >> 2, c = tid & 3;
            const char* sb  = (const char*)(Bh + (size_t)(n0 + row) * K + kt) + c * 16;
            const char* sbl = (const char*)(Bl + (size_t)(n0 + row) * K + kt) + c * 16;
            cp16(smem_u32(base + 20480 + row * 80 + c * 16), sb, 16);
            cp16(smem_u32(base + 25600 + row * 80 + c * 16), sbl, 16);
        }
        asm volatile("cp.async.commit_group;\n" ::: "memory");
    };

    load_stage(0, 0);
    if (nch > 1) load_stage(1, 32);

    for (int ch = 0; ch < nch; ++ch) {
        if (ch + 1 < nch) {
            asm volatile("cp.async.wait_group 1;\n" ::: "memory");
        } else {
            asm volatile("cp.async.wait_group 0;\n" ::: "memory");
        }
        __syncthreads();
        if (ch + 2 < nch) load_stage((ch + 2) % NSTAGE, (ch + 2) << 5);

        char* base = sm + (ch % NSTAGE) * STG_BYTES;
        __nv_bfloat16* sAh = (__nv_bfloat16*)base;
        __nv_bfloat16* sAl = (__nv_bfloat16*)(base + 10240);
        __nv_bfloat16* sBh = (__nv_bfloat16*)(base + 20480);
        __nv_bfloat16* sBl = (__nv_bfloat16*)(base + 25600);

        #pragma unroll
        for (int ks = 0; ks < 32; ks += 16) {
            uint32_t ah[2][4], al[2][4], bh[4][2], bl[4][2];
            #pragma unroll
            for (int mi = 0; mi < 2; ++mi) {
                int r = wm * 32 + mi * 16 + (lane & 15);
                int c = ks + ((lane >> 4) << 3);
                LDM_X4(ah[mi][0], ah[mi][1], ah[mi][2], ah[mi][3], smem_u32(&sAh[r * 40 + c]));
                LDM_X4(al[mi][0], al[mi][1], al[mi][2], al[mi][3], smem_u32(&sAl[r * 40 + c]));
            }
            #pragma unroll
            for (int ni = 0; ni < 4; ++ni) {
                int r = wn * 32 + ni * 8 + (lane & 7);
                int c = ks + (((lane >> 3) & 1) << 3);
                LDM_X2(bh[ni][0], bh[ni][1], smem_u32(&sBh[r * 40 + c]));
                LDM_X2(bl[ni][0], bl[ni][1], smem_u32(&sBl[r * 40 + c]));
            }
            #pragma unroll
            for (int mi = 0; mi < 2; ++mi)
                #pragma unroll
                for (int ni = 0; ni < 4; ++ni) {
                    MMA_BF16(acc[mi][ni], ah[mi], bh[ni]);
                    MMA_BF16(acc[mi][ni], ah[mi], bl[ni]);
                    MMA_BF16(acc[mi][ni], al[mi], bh[ni]);
                }
        }
        // trailing sync: stage (ch-1) fully consumed by ALL warps before any thread
        // can reach the prefetch that overwrites it in iteration ch+1
        __syncthreads();
    }

    // ---- epilogue ----
    const int g = lane >> 2, tg = lane & 3;
    #pragma unroll
    for (int mi = 0; mi < 2; ++mi) {
        #pragma unroll
        for (int ni = 0; ni < 4; ++ni) {
            int col = n0 + wn * 32 + ni * 8 + tg * 2;
            float b0v, b1v;
            if constexpr (EPI == 3) {
                b0v = (col < 256) ? bias[col] : bias2[col - 256];
                b1v = (col + 1 < 256) ? bias[col + 1] : bias2[col + 1 - 256];
            } else {
                b0v = bias[col]; b1v = bias[col + 1];
            }
            #pragma unroll
            for (int half = 0; half < 2; ++half) {
                int gm = m0 + wm * 32 + mi * 16 + g + half * 8;
                if (gm >= M) continue;
                float v0 = acc[mi][ni][half * 2 + 0] + b0v;
                float v1 = acc[mi][ni][half * 2 + 1] + b1v;
                if constexpr (EPI == 1) {
                    v0 = fmaxf(v0, 0.f); v1 = fmaxf(v1, 0.f);
                    __nv_bfloat162 hh = __floats2bfloat162_rn(v0, v1);
                    __nv_bfloat162 ll = __floats2bfloat162_rn(v0 - __bfloat162float(hh.x),
                                                              v1 - __bfloat162float(hh.y));
                    *(__nv_bfloat162*)((__nv_bfloat16*)Cv  + (size_t)gm * N + col) = hh;
                    *(__nv_bfloat162*)((__nv_bfloat16*)Cv2 + (size_t)gm * N + col) = ll;
                } else if constexpr (EPI == 2) {
                    int b = gm / Sc, s = gm - b * Sc;
                    int h = col >> 5, dh = col & 31;
                    __half* cp = (__half*)Cv + (((size_t)(b * Hc + h)) * Sc + s) * DHc + dh;
                    *(__half2*)cp = __floats2half2_rn(v0, v1);
                } else if constexpr (EPI == 3) {
                    float* cp = (float*)Cv + (size_t)gm * 384 + col;
                    cp[0] = v0; cp[1] = v1;
                } else {
                    float* cp = (float*)Cv + (size_t)gm * N + col;
                    cp[0] = v0; cp[1] = v1;
                }
            }
        }
    }
}

// ---------------- elementwise ----------------
__global__ void copy4_k(const float4* __restrict__ a, float4* __restrict__ c, int n4) {
    int i = blockIdx.x * blockDim.x + threadIdx.x;
    if (i < n4) c[i] = a[i];
}

// ---------------- softmax over 16 attn logits in fused buffer [M,384] ----------------
__global__ void softmax16_k(float* __restrict__ oa, int total) {
    int i = blockIdx.x * blockDim.x + threadIdx.x;
    if (i >= total) return;
    int m = i >> 3, h = i & 7;
    float* p = oa + (size_t)m * 384 + 256 + h * 16;
    float v[16];
    #pragma unroll
    for (int j = 0; j < 4; ++j) {
        float4 t = ((const float4*)p)[j];
        v[j*4+0] = t.x; v[j*4+1] = t.y; v[j*4+2] = t.z; v[j*4+3] = t.w;
    }
    float mx = v[0];
    #pragma unroll
    for (int j = 1; j < 16; ++j) mx = fmaxf(mx, v[j]);
    float s = 0.f;
    #pragma unroll
    for (int j = 0; j < 16; ++j) { v[j] = expf(v[j] - mx); s += v[j]; }
    float inv = 1.f / s;
    #pragma unroll
    for (int j = 0; j < 4; ++j) {
        float4 t = make_float4(v[j*4+0]*inv, v[j*4+1]*inv, v[j*4+2]*inv, v[j*4+3]*inv);
        ((float4*)p)[j] = t;
    }
}

// ---------------- residual + LayerNorm; emits fp32 + bf16 hi/lo ----------------
__global__ void ln_k(const float* __restrict__ x, const float* __restrict__ y,
                     const float* __restrict__ g, const float* __restrict__ bt,
                     float* __restrict__ out,
                     __nv_bfloat16* __restrict__ outh, __nv_bfloat16* __restrict__ outl,
                     int rows)
{
    int w = (blockIdx.x * blockDim.x + threadIdx.x) >> 5;
    int lane = threadIdx.x & 31;
    if (w >= rows) return;
    const float* xp = x + (size_t)w * Dc;
    const float* yp = y + (size_t)w * Dc;
    float v[8];
    float s = 0.f;
    #pragma unroll
    for (int i = 0; i < 8; ++i) {
        int c = i * 32 + lane;
        v[i] = xp[c] + yp[c];
        s += v[i];
    }
    #pragma unroll
    for (int o = 16; o > 0; o >>= 1) s += __shfl_xor_sync(0xFFFFFFFFu, s, o);
    float mean = s * (1.f / 256.f);
    float vs = 0.f;
    #pragma unroll
    for (int i = 0; i < 8; ++i) { float d = v[i] - mean; vs += d * d; }
    #pragma unroll
    for (int o = 16; o > 0; o >>= 1) vs += __shfl_xor_sync(0xFFFFFFFFu, vs, o);
    float inv = rsqrtf(vs * (1.f / 256.f) + 1e-5f);
    float* op = out + (size_t)w * Dc;
    __nv_bfloat16* oh = outh + (size_t)w * Dc;
    __nv_bfloat16* ol = outl + (size_t)w * Dc;
    #pragma unroll
    for (int i = 0; i < 8; ++i) {
        int c = i * 32 + lane;
        float o = (v[i] - mean) * inv * g[c] + bt[c];
        op[c] = o;
        __nv_bfloat16 hv = __float2bfloat16(o);
        oh[c] = hv;
        ol[c] = __float2bfloat16(o - __bfloat162float(hv));
    }
}

// ---------------- deformable attention core (fp16 value, bf16 hi/lo output) ----------------
__global__ void deform_k(const float* __restrict__ oa, const __half* __restrict__ value,
                         const float* __restrict__ vr,
                         __nv_bfloat16* __restrict__ outh, __nv_bfloat16* __restrict__ outl)
{
    int w = (blockIdx.x * blockDim.x + threadIdx.x) >> 5;
    int lane = threadIdx.x & 31;
    if (w >= Mc * Hc) return;
    int h = w & 7;
    int m = w >> 3;
    int b = m / Sc, s = m - b * Sc;

    const int Wl_[4] = {100, 50, 25, 13};
    const int st_[4] = {0, 10000, 12500, 13125};

    int lq, ls;
    if (s < 10000)      { lq = 0; ls = s; }
    else if (s < 12500) { lq = 1; ls = s - 10000; }
    else if (s < 13125) { lq = 2; ls = s - 12500; }
    else                { lq = 3; ls = s - 13125; }
    int Wq = Wl_[lq];
    int iy = ls / Wq, ix = ls - iy * Wq;
    float rxb = (ix + 0.5f) / (vr[(b * LVLc + lq) * 2 + 0] * (float)Wq);
    float ryb = (iy + 0.5f) / (vr[(b * LVLc + lq) * 2 + 1] * (float)Wq);

    const float* offp = oa + (size_t)m * 384 + h * 32;
    const float* attp = oa + (size_t)m * 384 + 256 + h * 16;
    const __half* vb = value + ((size_t)(b * Hc + h)) * Sc * DHc;

    float acc = 0.f;
    #pragma unroll
    for (int lvl = 0; lvl < 4; ++lvl) {
        int Wl = Wl_[lvl];
        float refx = rxb * vr[(b * LVLc + lvl) * 2 + 0] * (float)Wl;
        float refy = ryb * vr[(b * LVLc + lvl) * 2 + 1] * (float)Wl;
        const __half* vl = vb + (size_t)st_[lvl] * DHc;
        #pragma unroll
        for (int p = 0; p < 4; ++p) {
            float ox = offp[lvl * 8 + p * 2];
            float oy = offp[lvl * 8 + p * 2 + 1];
            float a  = attp[lvl * 4 + p];
            float x = refx + ox - 0.5f;
            float y = refy + oy - 0.5f;
            float x0f = floorf(x), y0f = floorf(y);
            float wx1 = x - x0f, wx0 = 1.f - wx1;
            float wy1 = y - y0f, wy0 = 1.f - wy1;
            int x0 = (int)x0f, y0 = (int)y0f;
            float sv = 0.f;
            bool xin0 = (x0 >= 0) && (x0 < Wl);
            bool xin1 = (x0 + 1 >= 0) && (x0 + 1 < Wl);
            bool yin0 = (y0 >= 0) && (y0 < Wl);
            bool yin1 = (y0 + 1 >= 0) && (y0 + 1 < Wl);
            if (xin0 && yin0) sv += wx0 * wy0 * __half2float(vl[((size_t)y0 * Wl + x0) * DHc + lane]);
            if (xin1 && yin0) sv += wx1 * wy0 * __half2float(vl[((size_t)y0 * Wl + x0 + 1) * DHc + lane]);
            if (xin0 && yin1) sv += wx0 * wy1 * __half2float(vl[((size_t)(y0 + 1) * Wl + x0) * DHc + lane]);
            if (xin1 && yin1) sv += wx1 * wy1 * __half2float(vl[((size_t)(y0 + 1) * Wl + x0 + 1) * DHc + lane]);
            acc += a * sv;
        }
    }
    size_t oi = ((size_t)m * Hc + h) * DHc + lane;
    __nv_bfloat16 hv = __float2bfloat16(acc);
    outh[oi] = hv;
    outl[oi] = __float2bfloat16(acc - __bfloat162float(hv));
}

// ---------------- launch ----------------
extern "C" void kernel_launch(void* const* d_in, const int* in_sizes, int n_in,
                              void* d_out, int out_size)
{
    const float* in_src = (const float*)d_in[0];
    const float* in_pos = (const float*)d_in[1];
    const float* vr     = (const float*)d_in[2];
    const float* so_w   = (const float*)d_in[3];
    const float* so_b   = (const float*)d_in[4];
    const float* aw_w   = (const float*)d_in[5];
    const float* aw_b   = (const float*)d_in[6];
    const float* vp_w   = (const float*)d_in[7];
    const float* vp_b   = (const float*)d_in[8];
    const float* op_w   = (const float*)d_in[9];
    const float* op_b   = (const float*)d_in[10];
    const float* ln1g   = (const float*)d_in[11];
    const float* ln1b   = (const float*)d_in[12];
    const float* f1w    = (const float*)d_in[13];
    const float* f1b    = (const float*)d_in[14];
    const float* f2w    = (const float*)d_in[15];
    const float* f2b    = (const float*)d_in[16];
    const float* ln2g   = (const float*)d_in[17];
    const float* ln2b   = (const float*)d_in[18];

    float *p_src, *p_oa, *p_tmp, *p_src2;
    __half *p_valh;
    __nv_bfloat16 *p_srch, *p_srcl, *p_qh, *p_ql, *p_s2h, *p_s2l, *p_defh, *p_defl,
                  *p_ffnh, *p_ffnl, *p_wh, *p_wl;
    cudaGetSymbolAddress((void**)&p_src,  g_src);
    cudaGetSymbolAddress((void**)&p_valh, g_valh);
    cudaGetSymbolAddress((void**)&p_oa,   g_oa);
    cudaGetSymbolAddress((void**)&p_tmp,  g_tmp);
    cudaGetSymbolAddress((void**)&p_src2, g_src2);
    cudaGetSymbolAddress((void**)&p_srch, g_srch);
    cudaGetSymbolAddress((void**)&p_srcl, g_srcl);
    cudaGetSymbolAddress((void**)&p_qh,   g_qh);
    cudaGetSymbolAddress((void**)&p_ql,   g_ql);
    cudaGetSymbolAddress((void**)&p_s2h,  g_s2h);
    cudaGetSymbolAddress((void**)&p_s2l,  g_s2l);
    cudaGetSymbolAddress((void**)&p_defh, g_defh);
    cudaGetSymbolAddress((void**)&p_defl, g_defl);
    cudaGetSymbolAddress((void**)&p_ffnh, g_ffnh);
    cudaGetSymbolAddress((void**)&p_ffnl, g_ffnl);
    cudaGetSymbolAddress((void**)&p_wh,   g_wh);
    cudaGetSymbolAddress((void**)&p_wl,   g_wl);

    cudaFuncSetAttribute(mgemm_k<0>, cudaFuncAttributeMaxDynamicSharedMemorySize, SMEM_TOT);
    cudaFuncSetAttribute(mgemm_k<1>, cudaFuncAttributeMaxDynamicSharedMemorySize, SMEM_TOT);
    cudaFuncSetAttribute(mgemm_k<2>, cudaFuncAttributeMaxDynamicSharedMemorySize, SMEM_TOT);
    cudaFuncSetAttribute(mgemm_k<3>, cudaFuncAttributeMaxDynamicSharedMemorySize, SMEM_TOT);

    const int n4 = Mc * Dc / 4;
    const int eb = (n4 + 255) / 256;
    dim3 blk(256);
    const int MT = (Mc + 127) / 128;   // 208
    dim3 g256(4, MT), g384(6, MT), g1024(16, MT);

    // launch 0: all weight prep in ONE kernel
    wprep_all<<<(NLc * WPL + 255) / 256, blk>>>(vp_w, so_w, aw_w, op_w, f1w, f2w, p_wh, p_wl);
    // launch 1: split src (layer-0 A for value GEMM)
    split_k<<<eb, blk>>>((const float4*)in_src, nullptr, (uint2*)p_srch, (uint2*)p_srcl, n4);

    for (int l = 0; l < NLc; ++l) {
        size_t wb = (size_t)l * WPL;
        const float* curs = (l == 0) ? in_src : p_src;
        // q = src + pos, split to bf16 hi/lo
        split_k<<<eb, blk>>>((const float4*)curs, (const float4*)in_pos,
                             (uint2*)p_qh, (uint2*)p_ql, n4);
        // fused sampling-offset + attn-logit GEMM  (profiled slot)
        mgemm_k<3><<<g384, blk, SMEM_TOT>>>(p_qh, p_ql, p_wh + wb + OFF_SO, p_wl + wb + OFF_SO,
                                            so_b + l * 256, aw_b + l * 128, p_oa, nullptr, Mc, 384, 256);
        // value = src @ vp + vb  (fp16 transposed [B,H,S,DH])
        mgemm_k<2><<<g256, blk, SMEM_TOT>>>(p_srch, p_srcl, p_wh + wb + OFF_VP, p_wl + wb + OFF_VP,
                                            vp_b + l * Dc, nullptr, p_valh, nullptr, Mc, 256, 256);
        // softmax over 16 per (b,s,h)
        softmax16_k<<<(Mc * Hc + 255) / 256, blk>>>(p_oa, Mc * Hc);
        // deformable sampling -> bf16 hi/lo
        deform_k<<<(Mc * Hc * 32 + 255) / 256, blk>>>(p_oa, p_valh, vr, p_defh, p_defl);
        // out proj
        mgemm_k<0><<<g256, blk, SMEM_TOT>>>(p_defh, p_defl, p_wh + wb + OFF_OP, p_wl + wb + OFF_OP,
                                            op_b + l * Dc, nullptr, p_tmp, nullptr, Mc, 256, 256);
        // src2 = LN(src + attn_out), emits fp32 + hi/lo
        ln_k<<<(Mc + 7) / 8, blk>>>(curs, p_tmp, ln1g + l * Dc, ln1b + l * Dc,
                                    p_src2, p_s2h, p_s2l, Mc);
        // ffn1: relu -> bf16 hi/lo
        mgemm_k<1><<<g1024, blk, SMEM_TOT>>>(p_s2h, p_s2l, p_wh + wb + OFF_F1, p_wl + wb + OFF_F1,
                                             f1b + l * DFFc, nullptr, p_ffnh, p_ffnl, Mc, 1024, 256);
        // ffn2
        mgemm_k<0><<<g256, blk, SMEM_TOT>>>(p_ffnh, p_ffnl, p_wh + wb + OFF_F2, p_wl + wb + OFF_F2,
                                            f2b + l * Dc, nullptr, p_tmp, nullptr, Mc, 256, 1024);
        // src = LN(src2 + ffn), emits fp32 + hi/lo (next layer's value-GEMM A)
        ln_k<<<(Mc + 7) / 8, blk>>>(p_src2, p_tmp, ln2g + l * Dc, ln2b + l * Dc,
                                    p_src, p_srch, p_srcl, Mc);
    }

    copy4_k<<<eb, blk>>>((const float4*)p_src, (float4*)d_out, n4);
}

// round 12
// speedup vs baseline: 1.5338x; 1.5338x over previous
#include <cuda_runtime.h>
#include <cuda_fp16.h>
#include <math.h>
#include <stdint.h>

// ---------------- problem constants ----------------
#define Bc   2
#define Sc   13294
#define Dc   256
#define Hc   8
#define LVLc 4
#define DFFc 1024
#define NLc  6
#define DHc  32
#define Mc   (Bc*Sc)          // 26588 token rows

// weight elems per layer and per-weight offsets (transposed [N,K] fp16)
#define WPL    753664
#define OFF_VP 0
#define OFF_SO 65536
#define OFF_AW 131072
#define OFF_OP 163840
#define OFF_F1 229376
#define OFF_F2 491520

// ---------------- device scratch (no allocation allowed) ----------------
__device__ float  g_src [Mc*Dc];
__device__ __half g_valh[Mc*Dc];          // value fp16 [B,H,S,DH]
__device__ float  g_oa  [Mc*384];         // fused: [0,256)=offsets, [256,384)=attn
__device__ float  g_tmp [Mc*Dc];
__device__ float  g_src2[Mc*Dc];
__device__ __half g_srch[Mc*Dc];
__device__ __half g_qh  [Mc*Dc];
__device__ __half g_s2h [Mc*Dc];
__device__ __half g_defh[Mc*Dc];
__device__ __half g_ffnh[Mc*DFFc];
__device__ __half g_wh  [NLc*WPL];

// ---------------- helpers ----------------
__device__ __forceinline__ uint32_t smem_u32(const void* p) {
    uint32_t a;
    asm("{ .reg .u64 t; cvta.to.shared.u64 t, %1; cvt.u32.u64 %0, t; }" : "=r"(a) : "l"(p));
    return a;
}
__device__ __forceinline__ void cp16(uint32_t d, const void* s, int pbytes) {
    asm volatile("cp.async.cg.shared.global [%0], [%1], 16, %2;\n"
        :: "r"(d), "l"(s), "r"(pbytes) : "memory");
}
#define LDM_X4(r0,r1,r2,r3,addr) \
    asm volatile("ldmatrix.sync.aligned.m8n8.x4.shared.b16 {%0,%1,%2,%3}, [%4];" \
        : "=r"(r0),"=r"(r1),"=r"(r2),"=r"(r3) : "r"(addr))
#define LDM_X2(r0,r1,addr) \
    asm volatile("ldmatrix.sync.aligned.m8n8.x2.shared.b16 {%0,%1}, [%2];" \
        : "=r"(r0),"=r"(r1) : "r"(addr))
#define MMA_F16(c, a, b) \
    asm volatile("mma.sync.aligned.m16n8k16.row.col.f32.f16.f16.f32 " \
        "{%0,%1,%2,%3}, {%4,%5,%6,%7}, {%8,%9}, {%0,%1,%2,%3};" \
        : "+f"((c)[0]),"+f"((c)[1]),"+f"((c)[2]),"+f"((c)[3]) \
        : "r"((a)[0]),"r"((a)[1]),"r"((a)[2]),"r"((a)[3]), "r"((b)[0]),"r"((b)[1]))

// ---------------- fused weight prep: all layers, fp16 [N,K], one launch ----------------
__global__ void wprep_all(const float* __restrict__ vp, const float* __restrict__ so,
                          const float* __restrict__ aw, const float* __restrict__ op,
                          const float* __restrict__ f1, const float* __restrict__ f2,
                          __half* __restrict__ wh)
{
    int idx = blockIdx.x * blockDim.x + threadIdx.x;
    if (idx >= NLc * WPL) return;
    int l = idx / WPL, r = idx - l * WPL;
    const float* W; int K, N, off;
    if (r < OFF_SO)      { W = vp + (size_t)l * 65536;  off = OFF_VP; K = 256;  N = 256; }
    else if (r < OFF_AW) { W = so + (size_t)l * 65536;  off = OFF_SO; K = 256;  N = 256; }
    else if (r < OFF_OP) { W = aw + (size_t)l * 32768;  off = OFF_AW; K = 256;  N = 128; }
    else if (r < OFF_F1) { W = op + (size_t)l * 65536;  off = OFF_OP; K = 256;  N = 256; }
    else if (r < OFF_F2) { W = f1 + (size_t)l * 262144; off = OFF_F1; K = 256;  N = 1024; }
    else                 { W = f2 + (size_t)l * 262144; off = OFF_F2; K = 1024; N = 256; }
    int ri = r - off;
    int k = ri / N, n = ri - k * N;
    wh[(size_t)l * WPL + off + (size_t)n * K + k] = __float2half(W[(size_t)k * N + n]);
}

// ---------------- streaming fp32 -> fp16 (optionally a+b) ----------------
__global__ void split_k(const float4* __restrict__ a, const float4* __restrict__ b,
                        uint2* __restrict__ hi, int n4)
{
    int i = blockIdx.x * blockDim.x + threadIdx.x;
    if (i >= n4) return;
    float4 v = a[i];
    if (b) { float4 p = b[i]; v.x += p.x; v.y += p.y; v.z += p.z; v.w += p.w; }
    __half2 h01 = __floats2half2_rn(v.x, v.y);
    __half2 h23 = __floats2half2_rn(v.z, v.w);
    hi[i] = make_uint2(*(uint32_t*)&h01, *(uint32_t*)&h23);
}

// ---------------- pipelined fp16 tensor GEMM (fp32 accum) ----------------
// C = A @ W + bias.  A fp16 [M,K], W fp16 [N,K] (k-contiguous = .col operand).
// CTA tile 128(M)x128(N), 8 warps as 2(M)x4(N), warp tile 64x32, BK=32,
// 3-stage cp.async pipeline.
// EPI: 0=bias fp32; 1=bias+relu -> fp16; 2=bias -> fp16 transposed [B,H,S,DH];
//      3=dual bias fp32, row stride 384.
// smem stage: A 128x80B = 10240 | B 128x80B = 10240 -> 20480 B
#define STG_BYTES 20480
#define NSTAGE    3
#define SMEM_TOT  (NSTAGE*STG_BYTES)

template<int EPI>
__global__ void __launch_bounds__(256, 2)
mgemm_k(const __half* __restrict__ Ah, const __half* __restrict__ Bh,
        const float* __restrict__ bias, const float* __restrict__ bias2,
        void* __restrict__ Cv, int M, int N, int K)
{
    extern __shared__ char sm[];
    const int tid = threadIdx.x, warp = tid >> 5, lane = tid & 31;
    const int m0 = blockIdx.y * 128, n0 = blockIdx.x * 128;
    const int wm = warp >> 2, wn = warp & 3;   // 2 x 4 warp grid

    float acc[4][4][4] = {};
    const int nch = K >> 5;

    auto load_stage = [&](int st, int kt) {
        char* base = sm + st * STG_BYTES;
        #pragma unroll
        for (int j = 0; j < 2; ++j) {
            int ci = j * 256 + tid, row = ci >> 2, c = ci & 3;
            int gm = m0 + row;
            int pb = (gm < M) ? 16 : 0;
            int gmc = (gm < M) ? gm : (M - 1);
            cp16(smem_u32(base + row * 80 + c * 16),
                 (const char*)(Ah + (size_t)gmc * K + kt) + c * 16, pb);
        }
        #pragma unroll
        for (int j = 0; j < 2; ++j) {
            int ci = j * 256 + tid, row = ci >> 2, c = ci & 3;
            cp16(smem_u32(base + 10240 + row * 80 + c * 16),
                 (const char*)(Bh + (size_t)(n0 + row) * K + kt) + c * 16, 16);
        }
        asm volatile("cp.async.commit_group;\n" ::: "memory");
    };

    load_stage(0, 0);
    if (nch > 1) load_stage(1, 32);

    for (int ch = 0; ch < nch; ++ch) {
        if (ch + 1 < nch) {
            asm volatile("cp.async.wait_group 1;\n" ::: "memory");
        } else {
            asm volatile("cp.async.wait_group 0;\n" ::: "memory");
        }
        __syncthreads();
        if (ch + 2 < nch) load_stage((ch + 2) % NSTAGE, (ch + 2) << 5);

        char* base = sm + (ch % NSTAGE) * STG_BYTES;
        __half* sA = (__half*)base;
        __half* sB = (__half*)(base + 10240);

        #pragma unroll
        for (int ks = 0; ks < 32; ks += 16) {
            uint32_t a_[4][4], b_[4][2];
            #pragma unroll
            for (int mi = 0; mi < 4; ++mi) {
                int r = wm * 64 + mi * 16 + (lane & 15);
                int c = ks + ((lane >> 4) << 3);
                LDM_X4(a_[mi][0], a_[mi][1], a_[mi][2], a_[mi][3], smem_u32(&sA[r * 40 + c]));
            }
            #pragma unroll
            for (int ni = 0; ni < 4; ++ni) {
                int r = wn * 32 + ni * 8 + (lane & 7);
                int c = ks + (((lane >> 3) & 1) << 3);
                LDM_X2(b_[ni][0], b_[ni][1], smem_u32(&sB[r * 40 + c]));
            }
            #pragma unroll
            for (int mi = 0; mi < 4; ++mi)
                #pragma unroll
                for (int ni = 0; ni < 4; ++ni)
                    MMA_F16(acc[mi][ni], a_[mi], b_[ni]);
        }
        // trailing sync: stage (ch-1) fully consumed before any thread prefetches over it
        __syncthreads();
    }

    // ---- epilogue ----
    const int g = lane >> 2, tg = lane & 3;
    #pragma unroll
    for (int mi = 0; mi < 4; ++mi) {
        #pragma unroll
        for (int ni = 0; ni < 4; ++ni) {
            int col = n0 + wn * 32 + ni * 8 + tg * 2;
            float b0v, b1v;
            if constexpr (EPI == 3) {
                b0v = (col < 256) ? bias[col] : bias2[col - 256];
                b1v = (col + 1 < 256) ? bias[col + 1] : bias2[col + 1 - 256];
            } else {
                b0v = bias[col]; b1v = bias[col + 1];
            }
            #pragma unroll
            for (int half = 0; half < 2; ++half) {
                int gm = m0 + wm * 64 + mi * 16 + g + half * 8;
                if (gm >= M) continue;
                float v0 = acc[mi][ni][half * 2 + 0] + b0v;
                float v1 = acc[mi][ni][half * 2 + 1] + b1v;
                if constexpr (EPI == 1) {
                    v0 = fmaxf(v0, 0.f); v1 = fmaxf(v1, 0.f);
                    *(__half2*)((__half*)Cv + (size_t)gm * N + col) = __floats2half2_rn(v0, v1);
                } else if constexpr (EPI == 2) {
                    int b = gm / Sc, s = gm - b * Sc;
                    int h = col >> 5, dh = col & 31;   // col even -> col,col+1 same head
                    __half* cp = (__half*)Cv + (((size_t)(b * Hc + h)) * Sc + s) * DHc + dh;
                    *(__half2*)cp = __floats2half2_rn(v0, v1);
                } else if constexpr (EPI == 3) {
                    float* cp = (float*)Cv + (size_t)gm * 384 + col;
                    cp[0] = v0; cp[1] = v1;
                } else {
                    float* cp = (float*)Cv + (size_t)gm * N + col;
                    cp[0] = v0; cp[1] = v1;
                }
            }
        }
    }
}

// ---------------- elementwise ----------------
__global__ void copy4_k(const float4* __restrict__ a, float4* __restrict__ c, int n4) {
    int i = blockIdx.x * blockDim.x + threadIdx.x;
    if (i < n4) c[i] = a[i];
}

// ---------------- softmax over 16 attn logits in fused buffer [M,384] ----------------
__global__ void softmax16_k(float* __restrict__ oa, int total) {
    int i = blockIdx.x * blockDim.x + threadIdx.x;
    if (i >= total) return;
    int m = i >> 3, h = i & 7;
    float* p = oa + (size_t)m * 384 + 256 + h * 16;
    float v[16];
    #pragma unroll
    for (int j = 0; j < 4; ++j) {
        float4 t = ((const float4*)p)[j];
        v[j*4+0] = t.x; v[j*4+1] = t.y; v[j*4+2] = t.z; v[j*4+3] = t.w;
    }
    float mx = v[0];
    #pragma unroll
    for (int j = 1; j < 16; ++j) mx = fmaxf(mx, v[j]);
    float s = 0.f;
    #pragma unroll
    for (int j = 0; j < 16; ++j) { v[j] = expf(v[j] - mx); s += v[j]; }
    float inv = 1.f / s;
    #pragma unroll
    for (int j = 0; j < 4; ++j) {
        float4 t = make_float4(v[j*4+0]*inv, v[j*4+1]*inv, v[j*4+2]*inv, v[j*4+3]*inv);
        ((float4*)p)[j] = t;
    }
}

// ---------------- residual + LayerNorm; emits fp32 + fp16 ----------------
__global__ void ln_k(const float* __restrict__ x, const float* __restrict__ y,
                     const float* __restrict__ g, const float* __restrict__ bt,
                     float* __restrict__ out, __half* __restrict__ outh, int rows)
{
    int w = (blockIdx.x * blockDim.x + threadIdx.x) >> 5;
    int lane = threadIdx.x & 31;
    if (w >= rows) return;
    const float* xp = x + (size_t)w * Dc;
    const float* yp = y + (size_t)w * Dc;
    float v[8];
    float s = 0.f;
    #pragma unroll
    for (int i = 0; i < 8; ++i) {
        int c = i * 32 + lane;
        v[i] = xp[c] + yp[c];
        s += v[i];
    }
    #pragma unroll
    for (int o = 16; o > 0; o >>= 1) s += __shfl_xor_sync(0xFFFFFFFFu, s, o);
    float mean = s * (1.f / 256.f);
    float vs = 0.f;
    #pragma unroll
    for (int i = 0; i < 8; ++i) { float d = v[i] - mean; vs += d * d; }
    #pragma unroll
    for (int o = 16; o > 0; o >>= 1) vs += __shfl_xor_sync(0xFFFFFFFFu, vs, o);
    float inv = rsqrtf(vs * (1.f / 256.f) + 1e-5f);
    float* op = out + (size_t)w * Dc;
    __half* oh = outh + (size_t)w * Dc;
    #pragma unroll
    for (int i = 0; i < 8; ++i) {
        int c = i * 32 + lane;
        float o = (v[i] - mean) * inv * g[c] + bt[c];
        op[c] = o;
        oh[c] = __float2half(o);
    }
}

// ---------------- deformable attention core (fp16 value, fp16 output) ----------------
__global__ void deform_k(const float* __restrict__ oa, const __half* __restrict__ value,
                         const float* __restrict__ vr, __half* __restrict__ outh)
{
    int w = (blockIdx.x * blockDim.x + threadIdx.x) >> 5;
    int lane = threadIdx.x & 31;
    if (w >= Mc * Hc) return;
    int h = w & 7;
    int m = w >> 3;
    int b = m / Sc, s = m - b * Sc;

    const int Wl_[4] = {100, 50, 25, 13};
    const int st_[4] = {0, 10000, 12500, 13125};

    int lq, ls;
    if (s < 10000)      { lq = 0; ls = s; }
    else if (s < 12500) { lq = 1; ls = s - 10000; }
    else if (s < 13125) { lq = 2; ls = s - 12500; }
    else                { lq = 3; ls = s - 13125; }
    int Wq = Wl_[lq];
    int iy = ls / Wq, ix = ls - iy * Wq;
    float rxb = (ix + 0.5f) / (vr[(b * LVLc + lq) * 2 + 0] * (float)Wq);
    float ryb = (iy + 0.5f) / (vr[(b * LVLc + lq) * 2 + 1] * (float)Wq);

    const float* offp = oa + (size_t)m * 384 + h * 32;
    const float* attp = oa + (size_t)m * 384 + 256 + h * 16;
    const __half* vb = value + ((size_t)(b * Hc + h)) * Sc * DHc;

    float acc = 0.f;
    #pragma unroll
    for (int lvl = 0; lvl < 4; ++lvl) {
        int Wl = Wl_[lvl];
        float refx = rxb * vr[(b * LVLc + lvl) * 2 + 0] * (float)Wl;
        float refy = ryb * vr[(b * LVLc + lvl) * 2 + 1] * (float)Wl;
        const __half* vl = vb + (size_t)st_[lvl] * DHc;
        #pragma unroll
        for (int p = 0; p < 4; ++p) {
            float ox = offp[lvl * 8 + p * 2];
            float oy = offp[lvl * 8 + p * 2 + 1];
            float a  = attp[lvl * 4 + p];
            float x = refx + ox - 0.5f;
            float y = refy + oy - 0.5f;
            float x0f = floorf(x), y0f = floorf(y);
            float wx1 = x - x0f, wx0 = 1.f - wx1;
            float wy1 = y - y0f, wy0 = 1.f - wy1;
            int x0 = (int)x0f, y0 = (int)y0f;
            float sv = 0.f;
            bool xin0 = (x0 >= 0) && (x0 < Wl);
            bool xin1 = (x0 + 1 >= 0) && (x0 + 1 < Wl);
            bool yin0 = (y0 >= 0) && (y0 < Wl);
            bool yin1 = (y0 + 1 >= 0) && (y0 + 1 < Wl);
            if (xin0 && yin0) sv += wx0 * wy0 * __half2float(vl[((size_t)y0 * Wl + x0) * DHc + lane]);
            if (xin1 && yin0) sv += wx1 * wy0 * __half2float(vl[((size_t)y0 * Wl + x0 + 1) * DHc + lane]);
            if (xin0 && yin1) sv += wx0 * wy1 * __half2float(vl[((size_t)(y0 + 1) * Wl + x0) * DHc + lane]);
            if (xin1 && yin1) sv += wx1 * wy1 * __half2float(vl[((size_t)(y0 + 1) * Wl + x0 + 1) * DHc + lane]);
            acc += a * sv;
        }
    }
    outh[((size_t)m * Hc + h) * DHc + lane] = __float2half(acc);
}

// ---------------- launch ----------------
extern "C" void kernel_launch(void* const* d_in, const int* in_sizes, int n_in,
                              void* d_out, int out_size)
{
    const float* in_src = (const float*)d_in[0];
    const float* in_pos = (const float*)d_in[1];
    const float* vr     = (const float*)d_in[2];
    const float* so_w   = (const float*)d_in[3];
    const float* so_b   = (const float*)d_in[4];
    const float* aw_w   = (const float*)d_in[5];
    const float* aw_b   = (const float*)d_in[6];
    const float* vp_w   = (const float*)d_in[7];
    const float* vp_b   = (const float*)d_in[8];
    const float* op_w   = (const float*)d_in[9];
    const float* op_b   = (const float*)d_in[10];
    const float* ln1g   = (const float*)d_in[11];
    const float* ln1b   = (const float*)d_in[12];
    const float* f1w    = (const float*)d_in[13];
    const float* f1b    = (const float*)d_in[14];
    const float* f2w    = (const float*)d_in[15];
    const float* f2b    = (const float*)d_in[16];
    const float* ln2g   = (const float*)d_in[17];
    const float* ln2b   = (const float*)d_in[18];

    float *p_src, *p_oa, *p_tmp, *p_src2;
    __half *p_valh, *p_srch, *p_qh, *p_s2h, *p_defh, *p_ffnh, *p_wh;
    cudaGetSymbolAddress((void**)&p_src,  g_src);
    cudaGetSymbolAddress((void**)&p_valh, g_valh);
    cudaGetSymbolAddress((void**)&p_oa,   g_oa);
    cudaGetSymbolAddress((void**)&p_tmp,  g_tmp);
    cudaGetSymbolAddress((void**)&p_src2, g_src2);
    cudaGetSymbolAddress((void**)&p_srch, g_srch);
    cudaGetSymbolAddress((void**)&p_qh,   g_qh);
    cudaGetSymbolAddress((void**)&p_s2h,  g_s2h);
    cudaGetSymbolAddress((void**)&p_defh, g_defh);
    cudaGetSymbolAddress((void**)&p_ffnh, g_ffnh);
    cudaGetSymbolAddress((void**)&p_wh,   g_wh);

    cudaFuncSetAttribute(mgemm_k<0>, cudaFuncAttributeMaxDynamicSharedMemorySize, SMEM_TOT);
    cudaFuncSetAttribute(mgemm_k<1>, cudaFuncAttributeMaxDynamicSharedMemorySize, SMEM_TOT);
    cudaFuncSetAttribute(mgemm_k<2>, cudaFuncAttributeMaxDynamicSharedMemorySize, SMEM_TOT);
    cudaFuncSetAttribute(mgemm_k<3>, cudaFuncAttributeMaxDynamicSharedMemorySize, SMEM_TOT);

    const int n4 = Mc * Dc / 4;
    const int eb = (n4 + 255) / 256;
    dim3 blk(256);
    const int MT = (Mc + 127) / 128;   // 208
    dim3 g256(2, MT), g384(3, MT), g1024(8, MT);

    // launch 0: all weight prep in ONE kernel
    wprep_all<<<(NLc * WPL + 255) / 256, blk>>>(vp_w, so_w, aw_w, op_w, f1w, f2w, p_wh);
    // launch 1: src -> fp16 (layer-0 A for value GEMM)
    split_k<<<eb, blk>>>((const float4*)in_src, nullptr, (uint2*)p_srch, n4);

    for (int l = 0; l < NLc; ++l) {
        size_t wb = (size_t)l * WPL;
        const float* curs = (l == 0) ? in_src : p_src;
        // q = src + pos -> fp16
        split_k<<<eb, blk>>>((const float4*)curs, (const float4*)in_pos, (uint2*)p_qh, n4);
        // fused sampling-offset + attn-logit GEMM  (profiled slot)
        mgemm_k<3><<<g384, blk, SMEM_TOT>>>(p_qh, p_wh + wb + OFF_SO,
                                            so_b + l * 256, aw_b + l * 128, p_oa, Mc, 384, 256);
        // value = src @ vp + vb  (fp16 transposed [B,H,S,DH])
        mgemm_k<2><<<g256, blk, SMEM_TOT>>>(p_srch, p_wh + wb + OFF_VP,
                                            vp_b + l * Dc, nullptr, p_valh, Mc, 256, 256);
        // softmax over 16 per (b,s,h)
        softmax16_k<<<(Mc * Hc + 255) / 256, blk>>>(p_oa, Mc * Hc);
        // deformable sampling -> fp16
        deform_k<<<(Mc * Hc * 32 + 255) / 256, blk>>>(p_oa, p_valh, vr, p_defh);
        // out proj
        mgemm_k<0><<<g256, blk, SMEM_TOT>>>(p_defh, p_wh + wb + OFF_OP,
                                            op_b + l * Dc, nullptr, p_tmp, Mc, 256, 256);
        // src2 = LN(src + attn_out), emits fp32 + fp16
        ln_k<<<(Mc + 7) / 8, blk>>>(curs, p_tmp, ln1g + l * Dc, ln1b + l * Dc,
                                    p_src2, p_s2h, Mc);
        // ffn1: relu -> fp16
        mgemm_k<1><<<g1024, blk, SMEM_TOT>>>(p_s2h, p_wh + wb + OFF_F1,
                                             f1b + l * DFFc, nullptr, p_ffnh, Mc, 1024, 256);
        // ffn2
        mgemm_k<0><<<g256, blk, SMEM_TOT>>>(p_ffnh, p_wh + wb + OFF_F2,
                                            f2b + l * Dc, nullptr, p_tmp, Mc, 256, 1024);
        // src = LN(src2 + ffn), emits fp32 + fp16 (next layer's value-GEMM A)
        ln_k<<<(Mc + 7) / 8, blk>>>(p_src2, p_tmp, ln2g + l * Dc, ln2b + l * Dc,
                                    p_src, p_srch, Mc);
    }

    copy4_k<<<eb, blk>>>((const float4*)p_src, (float4*)d_out, n4);
}